// round 1
// baseline (speedup 1.0000x reference)
#include <cuda_runtime.h>
#include <cuda_bf16.h>
#include <math.h>

#define Bb 4
#define Cc 192
#define Hh 64
#define Wd 64
#define Ll 4096
#define Dd 384
#define Nst 16
#define Rr 12
#define BLD (Bb*Ll*Dd)

// scratch (static device allocations are allowed)
__device__ float g_part[2*128*Bb];
__device__ float g_sum[Bb], g_sumsq[Bb];
__device__ float g_u[BLD];      // snake order
__device__ float g_z[BLD];      // raster order
__device__ float g_uc[BLD];     // snake order
__device__ float g_delta[BLD];  // snake order
__device__ float g_y[BLD];      // snake order (scan output + Dskip)
__device__ float g_yg[BLD];     // raster order (gated)
__device__ float g_y2[BLD];     // raster order (after LE conv)
__device__ float g_dt[Bb*Ll*Rr];
__device__ float g_Bm[Bb*Ll*Nst];
__device__ float g_Cm[Bb*Ll*Nst];
__device__ float g_wf[Cc*Dd];   // fused proj_out @ out_proj

// ---------------- GroupNorm stats (deterministic two-stage) ----------------
__global__ void k_gnstats(const float* __restrict__ x){
    int b = blockIdx.y;
    const float4* xb = (const float4*)(x + (size_t)b*Cc*Ll);
    const int nt = (Cc*Ll)/4; // 196608
    float s = 0.f, q = 0.f;
    for (int i = blockIdx.x*blockDim.x + threadIdx.x; i < nt; i += gridDim.x*blockDim.x){
        float4 v = xb[i];
        s += v.x + v.y + v.z + v.w;
        q += v.x*v.x + v.y*v.y + v.z*v.z + v.w*v.w;
    }
    __shared__ float ss[256], qq[256];
    int t = threadIdx.x;
    ss[t] = s; qq[t] = q; __syncthreads();
    for (int o = 128; o > 0; o >>= 1){
        if (t < o){ ss[t] += ss[t+o]; qq[t] += qq[t+o]; }
        __syncthreads();
    }
    if (t == 0){
        g_part[b*128 + blockIdx.x] = ss[0];
        g_part[512 + b*128 + blockIdx.x] = qq[0];
    }
}

__global__ void k_gnfin(){
    int b = blockIdx.x, t = threadIdx.x; // 128 threads
    __shared__ float ss[128], qq[128];
    ss[t] = g_part[b*128 + t];
    qq[t] = g_part[512 + b*128 + t];
    __syncthreads();
    for (int o = 64; o > 0; o >>= 1){
        if (t < o){ ss[t] += ss[t+o]; qq[t] += qq[t+o]; }
        __syncthreads();
    }
    if (t == 0){ g_sum[b] = ss[0]; g_sumsq[b] = qq[0]; }
}

// ---------------- fused final weight: Wf[o,d] = sum_c P[o,c]*Wout[c,d] ------
__global__ void k_wfuse(const float* __restrict__ P, const float* __restrict__ Wo){
    int idx = blockIdx.x*256 + threadIdx.x;
    if (idx >= Cc*Dd) return;
    int o = idx / Dd, d = idx % Dd;
    float acc = 0.f;
    for (int c = 0; c < Cc; c++) acc = fmaf(P[o*Cc + c], Wo[c*Dd + d], acc);
    g_wf[idx] = acc;
}

// ---------------- GEMM1: GN-normalize + in_proj, write u(snake)/z(raster) --
// out[b,l,n] = sum_c xn[b,l,c] * W[n,c]   M=4096(per b), N=768, K=192
__global__ void k_inproj(const float* __restrict__ x, const float* __restrict__ gamma,
                         const float* __restrict__ beta, const float* __restrict__ W){
    const int b  = blockIdx.z;
    const int m0 = blockIdx.x*64;
    const int n0 = blockIdx.y*64;
    const int tid = threadIdx.x;
    const int tx = tid & 15, ty = tid >> 4;
    __shared__ float As[16][64];
    __shared__ float Bs[16][68];
    const float inv = 1.f/(float)(Cc*Ll);
    float mu   = g_sum[b]*inv;
    float var  = g_sumsq[b]*inv - mu*mu;
    float rstd = rsqrtf(var + 1e-5f);
    const float* xb = x + (size_t)b*Cc*Ll;
    float acc[4][4] = {};
    for (int k0 = 0; k0 < Cc; k0 += 16){
        #pragma unroll
        for (int i = 0; i < 4; i++){
            int idx = tid + i*256;
            int k = idx >> 6, m = idx & 63;
            float g = gamma[k0+k], bt = beta[k0+k];
            As[k][m] = (xb[(size_t)(k0+k)*Ll + m0+m] - mu)*rstd*g + bt;
        }
        #pragma unroll
        for (int i = 0; i < 4; i++){
            int idx = tid + i*256;
            int n = idx >> 4, k = idx & 15;
            Bs[k][n] = W[(size_t)(n0+n)*Cc + k0+k];
        }
        __syncthreads();
        #pragma unroll
        for (int kk = 0; kk < 16; kk++){
            float4 av = *(const float4*)&As[kk][ty*4];
            float4 bv = *(const float4*)&Bs[kk][tx*4];
            float a[4] = {av.x, av.y, av.z, av.w};
            float bb[4] = {bv.x, bv.y, bv.z, bv.w};
            #pragma unroll
            for (int i = 0; i < 4; i++)
                #pragma unroll
                for (int j = 0; j < 4; j++)
                    acc[i][j] = fmaf(a[i], bb[j], acc[i][j]);
        }
        __syncthreads();
    }
    #pragma unroll
    for (int i = 0; i < 4; i++){
        int m = m0 + ty*4 + i;
        int hh = m >> 6, ww = m & 63;
        int lp = (hh & 1) ? ((hh << 6) + (63 - ww)) : m;   // snake index
        #pragma unroll
        for (int j = 0; j < 4; j++){
            int n = n0 + tx*4 + j;
            if (n < Dd) g_u[((size_t)b*Ll + lp)*Dd + n] = acc[i][j];
            else        g_z[((size_t)b*Ll + m )*Dd + (n - Dd)] = acc[i][j];
        }
    }
}

// ---------------- causal depthwise conv1d (k=4) + SiLU ---------------------
__global__ void k_conv(const float* __restrict__ cw, const float* __restrict__ cb){
    int idx = blockIdx.x*256 + threadIdx.x;
    if (idx >= BLD) return;
    int d = idx % Dd; int bl = idx / Dd; int l = bl % Ll; int b = bl / Ll;
    float acc = cb[d];
    #pragma unroll
    for (int j = 0; j < 4; j++){
        int ls = l - 3 + j;
        if (ls >= 0) acc = fmaf(g_u[((size_t)b*Ll + ls)*Dd + d], cw[d*4 + j], acc);
    }
    float s = acc / (1.f + __expf(-acc));
    g_uc[idx] = s;
}

// ---------------- GEMM2: dbl = u_c @ x_proj_w^T (N=44 padded to 64) --------
__global__ void k_dbl(const float* __restrict__ Wx){
    const int m0 = blockIdx.x*64;   // row over B*L
    const int tid = threadIdx.x;
    const int tx = tid & 15, ty = tid >> 4;
    __shared__ float As[16][68];
    __shared__ float Bs[16][68];
    float acc[4][4] = {};
    for (int k0 = 0; k0 < Dd; k0 += 16){
        #pragma unroll
        for (int i = 0; i < 4; i++){
            int idx = tid + i*256;
            int m = idx >> 4, k = idx & 15;
            As[k][m] = g_uc[(size_t)(m0+m)*Dd + k0+k];
        }
        #pragma unroll
        for (int i = 0; i < 4; i++){
            int idx = tid + i*256;
            int n = idx >> 4, k = idx & 15;
            Bs[k][n] = (n < 44) ? Wx[(size_t)n*Dd + k0+k] : 0.f;
        }
        __syncthreads();
        #pragma unroll
        for (int kk = 0; kk < 16; kk++){
            float4 av = *(const float4*)&As[kk][ty*4];
            float4 bv = *(const float4*)&Bs[kk][tx*4];
            float a[4] = {av.x, av.y, av.z, av.w};
            float bb[4] = {bv.x, bv.y, bv.z, bv.w};
            #pragma unroll
            for (int i = 0; i < 4; i++)
                #pragma unroll
                for (int j = 0; j < 4; j++)
                    acc[i][j] = fmaf(a[i], bb[j], acc[i][j]);
        }
        __syncthreads();
    }
    #pragma unroll
    for (int i = 0; i < 4; i++){
        size_t row = m0 + ty*4 + i;
        #pragma unroll
        for (int j = 0; j < 4; j++){
            int e = tx*4 + j;
            if (e < 12)      g_dt[row*Rr + e]        = acc[i][j];
            else if (e < 28) g_Bm[row*Nst + (e-12)]  = acc[i][j];
            else if (e < 44) g_Cm[row*Nst + (e-28)]  = acc[i][j];
        }
    }
}

// ---------------- delta = softplus(dt @ dt_proj_w^T + b) -------------------
__global__ void k_delta(const float* __restrict__ dtw, const float* __restrict__ dtb){
    __shared__ float sw[Dd*13];
    for (int i = threadIdx.x; i < Dd*Rr; i += 256){
        int d = i / Rr, r = i % Rr;
        sw[d*13 + r] = dtw[i];
    }
    __syncthreads();
    for (int idx = blockIdx.x*256 + threadIdx.x; idx < BLD; idx += gridDim.x*256){
        int d = idx % Dd; size_t row = idx / Dd;
        const float* dtr = g_dt + row*Rr;
        float acc = dtb[d];
        #pragma unroll
        for (int r = 0; r < Rr; r++) acc = fmaf(dtr[r], sw[d*13 + r], acc);
        float sp = fmaxf(acc, 0.f) + log1pf(__expf(-fabsf(acc)));
        g_delta[idx] = sp;
    }
}

// ---------------- selective scan: thread=(d,n), warp-half reduce over n ----
__global__ void k_scan(const float* __restrict__ Alog, const float* __restrict__ Dsk){
    const int b = blockIdx.y;
    const int dBase = blockIdx.x*16;
    const int tid = threadIdx.x;
    const int dl = tid >> 4;       // 0..15 local d
    const int n  = tid & 15;       // state index
    const int d  = dBase + dl;
    float An  = -__expf(Alog[d*Nst + n]);
    float dsk = Dsk[d];
    __shared__ float s_d[64][16], s_u[64][16], s_B[64][16], s_C[64][16];
    float h = 0.f;
    const float* pD = g_delta + ((size_t)b*Ll)*Dd + dBase;
    const float* pU = g_uc    + ((size_t)b*Ll)*Dd + dBase;
    const float* pB = g_Bm    + ((size_t)b*Ll)*Nst;
    const float* pC = g_Cm    + ((size_t)b*Ll)*Nst;
    float*       pY = g_y     + ((size_t)b*Ll)*Dd + dBase;
    for (int l0 = 0; l0 < Ll; l0 += 64){
        #pragma unroll
        for (int i = 0; i < 4; i++){
            int idx = tid + i*256;
            int t = idx >> 4, c = idx & 15;
            s_d[t][c] = pD[(size_t)(l0+t)*Dd + c];
            s_u[t][c] = pU[(size_t)(l0+t)*Dd + c];
            s_B[t][c] = pB[(size_t)(l0+t)*Nst + c];
            s_C[t][c] = pC[(size_t)(l0+t)*Nst + c];
        }
        __syncthreads();
        #pragma unroll 4
        for (int t = 0; t < 64; t++){
            float dv = s_d[t][dl];
            float uv = s_u[t][dl];
            float dA = __expf(dv * An);
            h = fmaf(dA, h, (dv*uv) * s_B[t][n]);
            float p = h * s_C[t][n];
            p += __shfl_xor_sync(0xffffffffu, p, 8);
            p += __shfl_xor_sync(0xffffffffu, p, 4);
            p += __shfl_xor_sync(0xffffffffu, p, 2);
            p += __shfl_xor_sync(0xffffffffu, p, 1);
            if (n == 0) pY[(size_t)(l0+t)*Dd + dl] = p + uv*dsk;
        }
        __syncthreads();
    }
}

// ---------------- un-snake + gate with silu(z) ------------------------------
__global__ void k_gate(){
    int idx = blockIdx.x*256 + threadIdx.x;
    if (idx >= BLD) return;
    int d = idx % Dd; int bl = idx / Dd; int l = bl % Ll; int b = bl / Ll;
    int hh = l >> 6, ww = l & 63;
    int ls = (hh & 1) ? ((hh << 6) + (63 - ww)) : l;
    float yv = g_y[((size_t)b*Ll + ls)*Dd + d];
    float zv = g_z[idx];
    float sz = zv / (1.f + __expf(-zv));
    g_yg[idx] = yv * sz;
}

// ---------------- depthwise 3x3 local enhancement + residual ---------------
__global__ void k_le(const float* __restrict__ lw){
    int idx = blockIdx.x*256 + threadIdx.x;
    if (idx >= BLD) return;
    int d = idx % Dd; int bl = idx / Dd; int l = bl % Ll; int b = bl / Ll;
    int hh = l >> 6, ww = l & 63;
    float acc = g_yg[idx];
    #pragma unroll
    for (int dh = -1; dh <= 1; dh++){
        int h2 = hh + dh;
        if ((unsigned)h2 >= (unsigned)Hh) continue;
        #pragma unroll
        for (int dw = -1; dw <= 1; dw++){
            int w2 = ww + dw;
            if ((unsigned)w2 >= (unsigned)Wd) continue;
            acc = fmaf(g_yg[((size_t)b*Ll + (h2<<6) + w2)*Dd + d],
                       lw[d*9 + (dh+1)*3 + (dw+1)], acc);
        }
    }
    g_y2[idx] = acc;
}

// ---------------- GEMM3: out[b,o,l] = sum_d Wf[o,d]*y2[b,l,d] ---------------
__global__ void k_out(float* __restrict__ out){
    const int m0 = blockIdx.x*64;   // row over B*L
    const int n0 = blockIdx.y*64;   // o
    const int tid = threadIdx.x;
    const int tx = tid & 15, ty = tid >> 4;
    __shared__ float As[16][68];
    __shared__ float Bs[16][68];
    float acc[4][4] = {};
    for (int k0 = 0; k0 < Dd; k0 += 16){
        #pragma unroll
        for (int i = 0; i < 4; i++){
            int idx = tid + i*256;
            int m = idx >> 4, k = idx & 15;
            As[k][m] = g_y2[(size_t)(m0+m)*Dd + k0+k];
        }
        #pragma unroll
        for (int i = 0; i < 4; i++){
            int idx = tid + i*256;
            int n = idx >> 4, k = idx & 15;
            Bs[k][n] = g_wf[(size_t)(n0+n)*Dd + k0+k];
        }
        __syncthreads();
        #pragma unroll
        for (int kk = 0; kk < 16; kk++){
            float4 av = *(const float4*)&As[kk][ty*4];
            float4 bv = *(const float4*)&Bs[kk][tx*4];
            float a[4] = {av.x, av.y, av.z, av.w};
            float bb[4] = {bv.x, bv.y, bv.z, bv.w};
            #pragma unroll
            for (int i = 0; i < 4; i++)
                #pragma unroll
                for (int j = 0; j < 4; j++)
                    acc[i][j] = fmaf(a[i], bb[j], acc[i][j]);
        }
        __syncthreads();
    }
    int b = m0 >> 12;
    int lbase = (m0 & 4095) + ty*4;
    #pragma unroll
    for (int j = 0; j < 4; j++){
        int o = n0 + tx*4 + j;
        float4 v = make_float4(acc[0][j], acc[1][j], acc[2][j], acc[3][j]);
        *(float4*)&out[((size_t)b*Cc + o)*Ll + lbase] = v;
    }
}

extern "C" void kernel_launch(void* const* d_in, const int* in_sizes, int n_in,
                              void* d_out, int out_size){
    const float* x          = (const float*)d_in[0];
    const float* gn_gamma   = (const float*)d_in[1];
    const float* gn_beta    = (const float*)d_in[2];
    const float* in_proj_w  = (const float*)d_in[3];
    const float* conv1d_w   = (const float*)d_in[4];
    const float* conv1d_b   = (const float*)d_in[5];
    const float* x_proj_w   = (const float*)d_in[6];
    const float* dt_proj_w  = (const float*)d_in[7];
    const float* dt_proj_b  = (const float*)d_in[8];
    const float* A_log      = (const float*)d_in[9];
    const float* Dskip      = (const float*)d_in[10];
    const float* le_w       = (const float*)d_in[11];
    const float* out_proj_w = (const float*)d_in[12];
    const float* proj_out_w = (const float*)d_in[13];
    float* out = (float*)d_out;

    k_gnstats<<<dim3(128, Bb), 256>>>(x);
    k_gnfin<<<Bb, 128>>>();
    k_wfuse<<<(Cc*Dd + 255)/256, 256>>>(proj_out_w, out_proj_w);
    k_inproj<<<dim3(Ll/64, 768/64, Bb), 256>>>(x, gn_gamma, gn_beta, in_proj_w);
    k_conv<<<BLD/256, 256>>>(conv1d_w, conv1d_b);
    k_dbl<<<(Bb*Ll)/64, 256>>>(x_proj_w);
    k_delta<<<2048, 256>>>(dt_proj_w, dt_proj_b);
    k_scan<<<dim3(Dd/16, Bb), 256>>>(A_log, Dskip);
    k_gate<<<BLD/256, 256>>>();
    k_le<<<BLD/256, 256>>>(le_w);
    k_out<<<dim3((Bb*Ll)/64, Cc/64), 256>>>(out);
}

// round 2
// speedup vs baseline: 1.4964x; 1.4964x over previous
#include <cuda_runtime.h>
#include <cuda_bf16.h>
#include <math.h>

#define Bb 4
#define Cc 192
#define Hh 64
#define Wd 64
#define Ll 4096
#define Dd 384
#define Nst 16
#define Rr 12
#define BLD (Bb*Ll*Dd)
#define NCH 16
#define CHL 256   // chunk length (NCH*CHL = Ll)

// scratch
__device__ float g_part[2*128*Bb];
__device__ float g_sum[Bb], g_sumsq[Bb];
__device__ float g_u[BLD];      // snake order
__device__ float g_z[BLD];      // raster order
__device__ float g_uc[BLD];     // snake order
__device__ float g_delta[BLD];  // snake order
__device__ float g_y[BLD];      // snake order
__device__ float g_yg[BLD];     // raster order
__device__ float g_y2[BLD];     // raster order
__device__ float g_dt[Bb*Ll*Rr];
__device__ float g_Bm[Bb*Ll*Nst];
__device__ float g_Cm[Bb*Ll*Nst];
__device__ float g_wf[Cc*Dd];
__device__ float g_hend[Bb*NCH*Dd*Nst];
__device__ float g_aprod[Bb*NCH*Dd*Nst];
__device__ float g_hin[Bb*NCH*Dd*Nst];

// ---------------- GroupNorm stats ----------------
__global__ void k_gnstats(const float* __restrict__ x){
    int b = blockIdx.y;
    const float4* xb = (const float4*)(x + (size_t)b*Cc*Ll);
    const int nt = (Cc*Ll)/4;
    float s = 0.f, q = 0.f;
    for (int i = blockIdx.x*blockDim.x + threadIdx.x; i < nt; i += gridDim.x*blockDim.x){
        float4 v = xb[i];
        s += v.x + v.y + v.z + v.w;
        q += v.x*v.x + v.y*v.y + v.z*v.z + v.w*v.w;
    }
    __shared__ float ss[256], qq[256];
    int t = threadIdx.x;
    ss[t] = s; qq[t] = q; __syncthreads();
    for (int o = 128; o > 0; o >>= 1){
        if (t < o){ ss[t] += ss[t+o]; qq[t] += qq[t+o]; }
        __syncthreads();
    }
    if (t == 0){
        g_part[b*128 + blockIdx.x] = ss[0];
        g_part[512 + b*128 + blockIdx.x] = qq[0];
    }
}

__global__ void k_gnfin(){
    int b = blockIdx.x, t = threadIdx.x;
    __shared__ float ss[128], qq[128];
    ss[t] = g_part[b*128 + t];
    qq[t] = g_part[512 + b*128 + t];
    __syncthreads();
    for (int o = 64; o > 0; o >>= 1){
        if (t < o){ ss[t] += ss[t+o]; qq[t] += qq[t+o]; }
        __syncthreads();
    }
    if (t == 0){ g_sum[b] = ss[0]; g_sumsq[b] = qq[0]; }
}

// ---------------- fused final weight ----------------
__global__ void k_wfuse(const float* __restrict__ P, const float* __restrict__ Wo){
    int idx = blockIdx.x*256 + threadIdx.x;
    if (idx >= Cc*Dd) return;
    int o = idx / Dd, d = idx % Dd;
    float acc = 0.f;
    for (int c = 0; c < Cc; c++) acc = fmaf(P[o*Cc + c], Wo[c*Dd + d], acc);
    g_wf[idx] = acc;
}

// ---------------- GEMM1: GN + in_proj (128x128 tile, 8x8/thread) ----------
__global__ __launch_bounds__(256) void k_inproj(const float* __restrict__ x,
        const float* __restrict__ gamma, const float* __restrict__ beta,
        const float* __restrict__ W){
    const int b  = blockIdx.z;
    const int m0 = blockIdx.x*128;
    const int n0 = blockIdx.y*128;
    const int tid = threadIdx.x;
    const int tx = tid & 15, ty = tid >> 4;
    __shared__ float As[16][128];
    __shared__ float Bs[16][128];
    const float inv = 1.f/(float)(Cc*Ll);
    float mu   = g_sum[b]*inv;
    float var  = g_sumsq[b]*inv - mu*mu;
    float rstd = rsqrtf(var + 1e-5f);
    const float* xb = x + (size_t)b*Cc*Ll;
    float acc[8][8] = {};
    for (int k0 = 0; k0 < Cc; k0 += 16){
        #pragma unroll
        for (int i = 0; i < 2; i++){
            int lin = tid + i*256;          // 512 float4 slots
            int k = lin >> 5, m4 = lin & 31;
            float4 v = *(const float4*)&xb[(size_t)(k0+k)*Ll + m0 + m4*4];
            float g = gamma[k0+k]*rstd, bt = beta[k0+k] - mu*gamma[k0+k]*rstd;
            v.x = fmaf(v.x, g, bt); v.y = fmaf(v.y, g, bt);
            v.z = fmaf(v.z, g, bt); v.w = fmaf(v.w, g, bt);
            *(float4*)&As[k][m4*4] = v;
        }
        #pragma unroll
        for (int i = 0; i < 2; i++){
            int lin = tid + i*256;          // 512 slots, 4 k's each
            int n = lin & 127, kq = lin >> 7;
            float4 v = *(const float4*)&W[(size_t)(n0+n)*Cc + k0 + kq*4];
            Bs[kq*4+0][n] = v.x; Bs[kq*4+1][n] = v.y;
            Bs[kq*4+2][n] = v.z; Bs[kq*4+3][n] = v.w;
        }
        __syncthreads();
        #pragma unroll
        for (int kk = 0; kk < 16; kk++){
            float a[8], bb[8];
            *(float4*)&a[0]  = *(const float4*)&As[kk][ty*8];
            *(float4*)&a[4]  = *(const float4*)&As[kk][ty*8+4];
            *(float4*)&bb[0] = *(const float4*)&Bs[kk][tx*8];
            *(float4*)&bb[4] = *(const float4*)&Bs[kk][tx*8+4];
            #pragma unroll
            for (int i = 0; i < 8; i++)
                #pragma unroll
                for (int j = 0; j < 8; j++)
                    acc[i][j] = fmaf(a[i], bb[j], acc[i][j]);
        }
        __syncthreads();
    }
    if (n0 < Dd){
        #pragma unroll
        for (int i = 0; i < 8; i++){
            int m = m0 + ty*8 + i;
            int hh = m >> 6, ww = m & 63;
            int lp = (hh & 1) ? ((hh << 6) + (63 - ww)) : m;
            float* p = &g_u[((size_t)b*Ll + lp)*Dd + n0 + tx*8];
            *(float4*)p     = make_float4(acc[i][0],acc[i][1],acc[i][2],acc[i][3]);
            *(float4*)(p+4) = make_float4(acc[i][4],acc[i][5],acc[i][6],acc[i][7]);
        }
    } else {
        #pragma unroll
        for (int i = 0; i < 8; i++){
            int m = m0 + ty*8 + i;
            float* p = &g_z[((size_t)b*Ll + m)*Dd + (n0-Dd) + tx*8];
            *(float4*)p     = make_float4(acc[i][0],acc[i][1],acc[i][2],acc[i][3]);
            *(float4*)(p+4) = make_float4(acc[i][4],acc[i][5],acc[i][6],acc[i][7]);
        }
    }
}

// ---------------- causal depthwise conv1d + SiLU ----------------
__global__ void k_conv(const float* __restrict__ cw, const float* __restrict__ cb){
    int idx = blockIdx.x*256 + threadIdx.x;
    if (idx >= BLD) return;
    int d = idx % Dd; int bl = idx / Dd; int l = bl % Ll; int b = bl / Ll;
    float acc = cb[d];
    #pragma unroll
    for (int j = 0; j < 4; j++){
        int ls = l - 3 + j;
        if (ls >= 0) acc = fmaf(g_u[((size_t)b*Ll + ls)*Dd + d], cw[d*4 + j], acc);
    }
    g_uc[idx] = acc / (1.f + __expf(-acc));
}

// ---------------- GEMM2: dbl = u_c @ x_proj_w^T ----------------
__global__ void k_dbl(const float* __restrict__ Wx){
    const int m0 = blockIdx.x*64;
    const int tid = threadIdx.x;
    const int tx = tid & 15, ty = tid >> 4;
    __shared__ float As[16][68];
    __shared__ float Bs[16][68];
    float acc[4][4] = {};
    for (int k0 = 0; k0 < Dd; k0 += 16){
        #pragma unroll
        for (int i = 0; i < 4; i++){
            int idx = tid + i*256;
            int m = idx >> 4, k = idx & 15;
            As[k][m] = g_uc[(size_t)(m0+m)*Dd + k0+k];
        }
        #pragma unroll
        for (int i = 0; i < 4; i++){
            int idx = tid + i*256;
            int n = idx >> 4, k = idx & 15;
            Bs[k][n] = (n < 44) ? Wx[(size_t)n*Dd + k0+k] : 0.f;
        }
        __syncthreads();
        #pragma unroll
        for (int kk = 0; kk < 16; kk++){
            float4 av = *(const float4*)&As[kk][ty*4];
            float4 bv = *(const float4*)&Bs[kk][tx*4];
            float a[4] = {av.x, av.y, av.z, av.w};
            float bb[4] = {bv.x, bv.y, bv.z, bv.w};
            #pragma unroll
            for (int i = 0; i < 4; i++)
                #pragma unroll
                for (int j = 0; j < 4; j++)
                    acc[i][j] = fmaf(a[i], bb[j], acc[i][j]);
        }
        __syncthreads();
    }
    #pragma unroll
    for (int i = 0; i < 4; i++){
        size_t row = m0 + ty*4 + i;
        #pragma unroll
        for (int j = 0; j < 4; j++){
            int e = tx*4 + j;
            if (e < 12)      g_dt[row*Rr + e]        = acc[i][j];
            else if (e < 28) g_Bm[row*Nst + (e-12)]  = acc[i][j];
            else if (e < 44) g_Cm[row*Nst + (e-28)]  = acc[i][j];
        }
    }
}

// ---------------- delta = softplus(dt @ dt_proj_w^T + b), fast -------------
__global__ void k_delta(const float* __restrict__ dtw, const float* __restrict__ dtb){
    __shared__ float sw[Dd*13];
    for (int i = threadIdx.x; i < Dd*Rr; i += 256){
        int d = i / Rr, r = i % Rr;
        sw[d*13 + r] = dtw[i];
    }
    __syncthreads();
    for (int idx = blockIdx.x*256 + threadIdx.x; idx < BLD; idx += gridDim.x*256){
        int d = idx % Dd; size_t row = idx / Dd;
        const float* dtr = g_dt + row*Rr;
        float acc = dtb[d];
        #pragma unroll
        for (int r = 0; r < Rr; r++) acc = fmaf(dtr[r], sw[d*13 + r], acc);
        g_delta[idx] = fmaxf(acc, 0.f) + __logf(1.f + __expf(-fabsf(acc)));
    }
}

// ---------------- scan pass A: per-chunk local end-state + decay product ---
__global__ void k_scanA(const float* __restrict__ Alog){
    const int b = blockIdx.z;
    const int ch = blockIdx.y;
    const int dBase = blockIdx.x*16;
    const int tid = threadIdx.x;
    const int dl = tid >> 4;
    const int n  = tid & 15;
    const int d  = dBase + dl;
    float An = -__expf(Alog[d*Nst + n]);
    __shared__ float s_d[64][16], s_u[64][16], s_B[64][16];
    float h = 0.f, S = 0.f;
    const size_t base = (size_t)b*Ll + (size_t)ch*CHL;
    const float* pD = g_delta + base*Dd + dBase;
    const float* pU = g_uc    + base*Dd + dBase;
    const float* pB = g_Bm    + base*Nst;
    for (int l0 = 0; l0 < CHL; l0 += 64){
        #pragma unroll
        for (int i = 0; i < 4; i++){
            int idx = tid + i*256;
            int t = idx >> 4, c = idx & 15;
            s_d[t][c] = pD[(size_t)(l0+t)*Dd + c];
            s_u[t][c] = pU[(size_t)(l0+t)*Dd + c];
            s_B[t][c] = pB[(size_t)(l0+t)*Nst + c];
        }
        __syncthreads();
        #pragma unroll 8
        for (int t = 0; t < 64; t++){
            float dv = s_d[t][dl];
            float dA = __expf(dv * An);
            h = fmaf(dA, h, (dv*s_u[t][dl]) * s_B[t][n]);
            S += dv;
        }
        __syncthreads();
    }
    size_t o = (((size_t)b*NCH + ch)*Dd + d)*Nst + n;
    g_hend[o]  = h;
    g_aprod[o] = __expf(An * S);
}

// ---------------- scan pass B: stitch chunk boundaries ---------------------
__global__ void k_scanB(){
    int gid = blockIdx.x*256 + threadIdx.x;   // 24576 threads
    int b = gid / (Dd*Nst);
    int rem = gid % (Dd*Nst);
    float hin = 0.f;
    #pragma unroll
    for (int c = 0; c < NCH; c++){
        size_t o = ((size_t)(b*NCH + c))*(Dd*Nst) + rem;
        g_hin[o] = hin;
        hin = g_aprod[o]*hin + g_hend[o];
    }
}

// ---------------- scan pass C: per-chunk scan with correct init, emit y ----
__global__ void k_scanC(const float* __restrict__ Alog, const float* __restrict__ Dsk){
    const int b = blockIdx.z;
    const int ch = blockIdx.y;
    const int dBase = blockIdx.x*16;
    const int tid = threadIdx.x;
    const int dl = tid >> 4;
    const int n  = tid & 15;
    const int d  = dBase + dl;
    float An  = -__expf(Alog[d*Nst + n]);
    float dsk = Dsk[d];
    __shared__ float s_d[64][16], s_u[64][16], s_B[64][16], s_C[64][16];
    float h = g_hin[(((size_t)b*NCH + ch)*Dd + d)*Nst + n];
    const size_t base = (size_t)b*Ll + (size_t)ch*CHL;
    const float* pD = g_delta + base*Dd + dBase;
    const float* pU = g_uc    + base*Dd + dBase;
    const float* pB = g_Bm    + base*Nst;
    const float* pC = g_Cm    + base*Nst;
    float*       pY = g_y     + base*Dd + dBase;
    for (int l0 = 0; l0 < CHL; l0 += 64){
        #pragma unroll
        for (int i = 0; i < 4; i++){
            int idx = tid + i*256;
            int t = idx >> 4, c = idx & 15;
            s_d[t][c] = pD[(size_t)(l0+t)*Dd + c];
            s_u[t][c] = pU[(size_t)(l0+t)*Dd + c];
            s_B[t][c] = pB[(size_t)(l0+t)*Nst + c];
            s_C[t][c] = pC[(size_t)(l0+t)*Nst + c];
        }
        __syncthreads();
        #pragma unroll 4
        for (int t = 0; t < 64; t++){
            float dv = s_d[t][dl];
            float uv = s_u[t][dl];
            float dA = __expf(dv * An);
            h = fmaf(dA, h, (dv*uv) * s_B[t][n]);
            float p = h * s_C[t][n];
            p += __shfl_xor_sync(0xffffffffu, p, 8);
            p += __shfl_xor_sync(0xffffffffu, p, 4);
            p += __shfl_xor_sync(0xffffffffu, p, 2);
            p += __shfl_xor_sync(0xffffffffu, p, 1);
            if (n == 0) pY[(size_t)(l0+t)*Dd + dl] = p + uv*dsk;
        }
        __syncthreads();
    }
}

// ---------------- un-snake + gate ----------------
__global__ void k_gate(){
    int idx = blockIdx.x*256 + threadIdx.x;
    if (idx >= BLD) return;
    int d = idx % Dd; int bl = idx / Dd; int l = bl % Ll; int b = bl / Ll;
    int hh = l >> 6, ww = l & 63;
    int ls = (hh & 1) ? ((hh << 6) + (63 - ww)) : l;
    float yv = g_y[((size_t)b*Ll + ls)*Dd + d];
    float zv = g_z[idx];
    g_yg[idx] = yv * (zv / (1.f + __expf(-zv)));
}

// ---------------- depthwise 3x3 + residual ----------------
__global__ void k_le(const float* __restrict__ lw){
    int idx = blockIdx.x*256 + threadIdx.x;
    if (idx >= BLD) return;
    int d = idx % Dd; int bl = idx / Dd; int l = bl % Ll; int b = bl / Ll;
    int hh = l >> 6, ww = l & 63;
    float acc = g_yg[idx];
    #pragma unroll
    for (int dh = -1; dh <= 1; dh++){
        int h2 = hh + dh;
        if ((unsigned)h2 >= (unsigned)Hh) continue;
        #pragma unroll
        for (int dw = -1; dw <= 1; dw++){
            int w2 = ww + dw;
            if ((unsigned)w2 >= (unsigned)Wd) continue;
            acc = fmaf(g_yg[((size_t)b*Ll + (h2<<6) + w2)*Dd + d],
                       lw[d*9 + (dh+1)*3 + (dw+1)], acc);
        }
    }
    g_y2[idx] = acc;
}

// ---------------- GEMM3: out (128x64 tile, 8x4/thread) ----------------
__global__ __launch_bounds__(256) void k_out(float* __restrict__ out){
    const int m0 = blockIdx.x*128;
    const int n0 = blockIdx.y*64;
    const int tid = threadIdx.x;
    const int tx = tid & 15, ty = tid >> 4;
    __shared__ float As[16][128];
    __shared__ float Bs[16][64];
    float acc[8][4] = {};
    for (int k0 = 0; k0 < Dd; k0 += 16){
        #pragma unroll
        for (int i = 0; i < 2; i++){
            int lin = tid + i*256;
            int m = lin & 127, kq = lin >> 7;
            float4 v = *(const float4*)&g_y2[(size_t)(m0+m)*Dd + k0 + kq*4];
            As[kq*4+0][m] = v.x; As[kq*4+1][m] = v.y;
            As[kq*4+2][m] = v.z; As[kq*4+3][m] = v.w;
        }
        {
            int n = tid & 63, kq = tid >> 6;
            float4 v = *(const float4*)&g_wf[(size_t)(n0+n)*Dd + k0 + kq*4];
            Bs[kq*4+0][n] = v.x; Bs[kq*4+1][n] = v.y;
            Bs[kq*4+2][n] = v.z; Bs[kq*4+3][n] = v.w;
        }
        __syncthreads();
        #pragma unroll
        for (int kk = 0; kk < 16; kk++){
            float a[8], bb[4];
            *(float4*)&a[0]  = *(const float4*)&As[kk][ty*8];
            *(float4*)&a[4]  = *(const float4*)&As[kk][ty*8+4];
            *(float4*)&bb[0] = *(const float4*)&Bs[kk][tx*4];
            #pragma unroll
            for (int i = 0; i < 8; i++)
                #pragma unroll
                for (int j = 0; j < 4; j++)
                    acc[i][j] = fmaf(a[i], bb[j], acc[i][j]);
        }
        __syncthreads();
    }
    int b = m0 >> 12;
    int lbase = (m0 & 4095) + ty*8;
    #pragma unroll
    for (int j = 0; j < 4; j++){
        int o = n0 + tx*4 + j;
        float* p = &out[((size_t)b*Cc + o)*Ll + lbase];
        *(float4*)p     = make_float4(acc[0][j], acc[1][j], acc[2][j], acc[3][j]);
        *(float4*)(p+4) = make_float4(acc[4][j], acc[5][j], acc[6][j], acc[7][j]);
    }
}

extern "C" void kernel_launch(void* const* d_in, const int* in_sizes, int n_in,
                              void* d_out, int out_size){
    const float* x          = (const float*)d_in[0];
    const float* gn_gamma   = (const float*)d_in[1];
    const float* gn_beta    = (const float*)d_in[2];
    const float* in_proj_w  = (const float*)d_in[3];
    const float* conv1d_w   = (const float*)d_in[4];
    const float* conv1d_b   = (const float*)d_in[5];
    const float* x_proj_w   = (const float*)d_in[6];
    const float* dt_proj_w  = (const float*)d_in[7];
    const float* dt_proj_b  = (const float*)d_in[8];
    const float* A_log      = (const float*)d_in[9];
    const float* Dskip      = (const float*)d_in[10];
    const float* le_w       = (const float*)d_in[11];
    const float* out_proj_w = (const float*)d_in[12];
    const float* proj_out_w = (const float*)d_in[13];
    float* out = (float*)d_out;

    k_gnstats<<<dim3(128, Bb), 256>>>(x);
    k_gnfin<<<Bb, 128>>>();
    k_wfuse<<<(Cc*Dd + 255)/256, 256>>>(proj_out_w, out_proj_w);
    k_inproj<<<dim3(Ll/128, 768/128, Bb), 256>>>(x, gn_gamma, gn_beta, in_proj_w);
    k_conv<<<BLD/256, 256>>>(conv1d_w, conv1d_b);
    k_dbl<<<(Bb*Ll)/64, 256>>>(x_proj_w);
    k_delta<<<2048, 256>>>(dt_proj_w, dt_proj_b);
    k_scanA<<<dim3(Dd/16, NCH, Bb), 256>>>(A_log);
    k_scanB<<<(Bb*Dd*Nst)/256, 256>>>();
    k_scanC<<<dim3(Dd/16, NCH, Bb), 256>>>(A_log, Dskip);
    k_gate<<<BLD/256, 256>>>();
    k_le<<<BLD/256, 256>>>(le_w);
    k_out<<<dim3((Bb*Ll)/128, Cc/64), 256>>>(out);
}